// round 11
// baseline (speedup 1.0000x reference)
#include <cuda_runtime.h>
#include <cstdint>
#include <cstdio>

#define TSTEPS 4096
#define NTT    4095
#define VDIM   88
#define HDIM   512
#define RDIM   512
#define GS     20

typedef unsigned long long ull;

// ---------------------------------------------------------------------------
// Scratch (static device globals — no runtime allocation allowed)
// ---------------------------------------------------------------------------
__device__ float  g_a    [NTT * RDIM];
__device__ float  g_uprev[NTT * RDIM];
__device__ float  g_bht  [NTT * HDIM];
__device__ float  g_bvt  [NTT * VDIM];
__device__ float  g_h    [NTT * HDIM];
__device__ float  g_v    [NTT * VDIM];
__device__ float  g_wT   [VDIM * HDIM];
__device__ double g_ce   [256];
__device__ double g_n2uv [64];
__device__ double g_n2uh [64];

// ---------------------------------------------------------------------------
// Helpers: packed fp32x2 ops (componentwise IEEE fp32 — order-preserving)
// ---------------------------------------------------------------------------
__device__ __forceinline__ ull fma2_(ull a, ull b, ull c) {
    ull d; asm("fma.rn.f32x2 %0, %1, %2, %3;" : "=l"(d) : "l"(a), "l"(b), "l"(c));
    return d;
}
__device__ __forceinline__ ull add2_(ull a, ull b) {
    ull d; asm("add.rn.f32x2 %0, %1, %2;" : "=l"(d) : "l"(a), "l"(b));
    return d;
}
__device__ __forceinline__ ull pack2_(float lo, float hi) {
    ull d; asm("mov.b64 %0, {%1, %2};" : "=l"(d) : "f"(lo), "f"(hi));
    return d;
}
__device__ __forceinline__ ull dup2_(float v) {
    ull d; asm("mov.b64 %0, {%1, %1};" : "=l"(d) : "f"(v));
    return d;
}
__device__ __forceinline__ float lo2_(ull v) { return __uint_as_float((unsigned)v); }
__device__ __forceinline__ float hi2_(ull v) { return __uint_as_float((unsigned)(v >> 32)); }

__device__ __forceinline__ void cluster_sync_() {
    asm volatile("barrier.cluster.arrive.aligned;\n\t"
                 "barrier.cluster.wait.aligned;" ::: "memory");
}
__device__ __forceinline__ uint32_t smem_u32(const void* p) {
    return (uint32_t)__cvta_generic_to_shared(p);
}

// mbarrier helpers (cluster scope)
#define MBAR_INIT(mb, cnt) \
    asm volatile("mbarrier.init.shared.b64 [%0], %1;" :: "r"(mb), "r"(cnt) : "memory")

#define MBAR_ARRIVE_REL_CLUSTER(mb_remote) \
    asm volatile("mbarrier.arrive.release.cluster.shared::cluster.b64 _, [%0];" \
                 :: "r"(mb_remote) : "memory")

#define WAITP_ACQ_CLUSTER(mb, par) do {                                            \
    uint32_t done_;                                                                \
    asm volatile("{\n\t.reg .pred P;\n\t"                                          \
        "mbarrier.try_wait.parity.acquire.cluster.shared::cta.b64 P, [%1], %2;\n\t"\
        "selp.b32 %0, 1, 0, P;\n\t}"                                               \
        : "=r"(done_) : "r"(mb), "r"(par) : "memory");                             \
    while (!done_) {                                                               \
        asm volatile("{\n\t.reg .pred P;\n\t"                                      \
            "mbarrier.try_wait.parity.acquire.cluster.shared::cta.b64 P, [%1], %2, 0x989680;\n\t" \
            "selp.b32 %0, 1, 0, P;\n\t}"                                           \
            : "=r"(done_) : "r"(mb), "r"(par) : "memory");                         \
    }                                                                              \
} while (0)

// ---------------------------------------------------------------------------
// NT GEMM: C[m][n] = sum_k A[m][k]*B[n][k] + bias[m*bs+n]; optional Bernoulli
// epilogue. Tile (16*TM) x 64, K-chunk 16, 256 threads, TM x 4 per thread.
// FFMA2 pairs adjacent M rows; each output's k-ascending chain is bit-exact
// vs the round-8 scalar kernel. Requires lda, ldb, K all % 4 == 0 (true for
// every call site: 88 / 512). Register-double-buffered staging, vectorized
// global loads. __launch_bounds__(256,2) lifts the 64-reg cap that was
// spilling accumulators to local memory.
// ---------------------------------------------------------------------------
template <int TM>
__global__ void __launch_bounds__(256, 2) gemm2_nt(
    const float* __restrict__ A, int lda,
    const float* __restrict__ B, int ldb,
    const float* __restrict__ bias, int bias_stride,
    const float* __restrict__ rnd, int rnd_stride,
    float* __restrict__ C, int ldc,
    int M, int N, int K)
{
    constexpr int BM  = 16 * TM;
    constexpr int KW  = TM;        // floats per thread (A staging, k dir)
    constexpr int TPR = 16 / KW;   // threads per A row
    constexpr int AQ  = KW / 4;    // float4s per thread (A staging)

    __shared__ __align__(16) float As[16][BM];
    __shared__ __align__(16) float Bs[16][64];

    const int tid = threadIdx.x;
    const int tx  = tid & 15;
    const int ty  = tid >> 4;
    const int m0  = blockIdx.x * BM;
    const int n0  = blockIdx.y * 64;

    // A staging map
    const int arow  = tid / TPR;
    const int akb   = (tid % TPR) * KW;
    const int am    = m0 + arow;
    const bool amok = (am < M);
    // B staging map
    const int brow  = tid >> 2;
    const int bkb   = (tid & 3) * 4;
    const int bn    = n0 + brow;
    const bool bnok = (bn < N);

    const float* Abase = A + (size_t)am * lda;
    const float* Bbase = B + (size_t)bn * ldb;
    const float4 z4 = make_float4(0.f, 0.f, 0.f, 0.f);

    float4 aR[AQ], bR;

    // preload chunk 0
#pragma unroll
    for (int q = 0; q < AQ; q++) {
        int k = akb + q * 4;
        aR[q] = (amok && k < K) ? *(const float4*)(Abase + k) : z4;
    }
    bR = (bnok && bkb < K) ? *(const float4*)(Bbase + bkb) : z4;

    ull acc[TM / 2][4];
#pragma unroll
    for (int i = 0; i < TM / 2; i++)
#pragma unroll
        for (int j = 0; j < 4; j++) acc[i][j] = 0ull;

    for (int k0 = 0; k0 < K; k0 += 16) {
        // commit staged regs to smem
#pragma unroll
        for (int q = 0; q < AQ; q++) {
            As[akb + q * 4 + 0][arow] = aR[q].x;
            As[akb + q * 4 + 1][arow] = aR[q].y;
            As[akb + q * 4 + 2][arow] = aR[q].z;
            As[akb + q * 4 + 3][arow] = aR[q].w;
        }
        Bs[bkb + 0][brow] = bR.x;
        Bs[bkb + 1][brow] = bR.y;
        Bs[bkb + 2][brow] = bR.z;
        Bs[bkb + 3][brow] = bR.w;
        __syncthreads();

        // prefetch next chunk while computing
        const int kn = k0 + 16;
        if (kn < K) {
#pragma unroll
            for (int q = 0; q < AQ; q++) {
                int k = kn + akb + q * 4;
                aR[q] = (amok && k < K) ? *(const float4*)(Abase + k) : z4;
            }
            int kb = kn + bkb;
            bR = (bnok && kb < K) ? *(const float4*)(Bbase + kb) : z4;
        }

#pragma unroll
        for (int k = 0; k < 16; k++) {
            float4 b4 = *(const float4*)&Bs[k][tx * 4];
            ull bb[4];
            bb[0] = dup2_(b4.x); bb[1] = dup2_(b4.y);
            bb[2] = dup2_(b4.z); bb[3] = dup2_(b4.w);
#pragma unroll
            for (int q = 0; q < TM / 4; q++) {
                ulonglong2 aa = *(const ulonglong2*)&As[k][ty * TM + q * 4];
#pragma unroll
                for (int c = 0; c < 4; c++) {
                    acc[2 * q + 0][c] = fma2_(aa.x, bb[c], acc[2 * q + 0][c]);
                    acc[2 * q + 1][c] = fma2_(aa.y, bb[c], acc[2 * q + 1][c]);
                }
            }
        }
        __syncthreads();
    }

    // Epilogue: acc[i] lo -> row ty*TM+2i, hi -> row ty*TM+2i+1
#pragma unroll
    for (int i = 0; i < TM / 2; i++) {
#pragma unroll
        for (int half = 0; half < 2; half++) {
            const int m = m0 + ty * TM + 2 * i + half;
            if (m >= M) continue;
#pragma unroll
            for (int c = 0; c < 4; c++) {
                const int n = n0 + tx * 4 + c;
                if (n >= N) continue;
                float v = half ? hi2_(acc[i][c]) : lo2_(acc[i][c]);
                float val = v + bias[(size_t)m * bias_stride + n];
                if (rnd) {
                    float s = 1.f / (1.f + expf(-val));
                    val = (s > rnd[(size_t)m * rnd_stride + n]) ? 1.f : 0.f;
                }
                C[(size_t)m * ldc + n] = val;
            }
        }
    }
}

// ---------------------------------------------------------------------------
// Sequential u recurrence: cluster of 8 CTAs, wuu register-resident.
// Packed FFMA2 dot (outputs o0/o1 and o2/o3 paired) + packed 64-bit butterfly
// — per-component accumulation order identical to the round-8 scalar version.
// Sync: dual alternating cluster mbarriers (count = 64 writers x 8 CTAs = 512)
// with arrive.release.cluster after DSMEM stores + local acquire wait, and a
// triple-buffered, pre-duplicated u array (LDS.64 feeds FFMA2 directly).
// ---------------------------------------------------------------------------
__global__ void __cluster_dims__(8, 1, 1) __launch_bounds__(512, 1)
recur_kernel(const float* __restrict__ wuu, const float* __restrict__ a,
             const float* __restrict__ u0, float* __restrict__ uprev)
{
    __shared__ __align__(16) ull u_d[3][RDIM];   // (u,u) duplicated pairs
    __shared__ __align__(8)  ull mbar[2];

    unsigned rank;
    asm("mov.u32 %0, %%cluster_ctarank;" : "=r"(rank));

    const int tid = threadIdx.x;
    const int w = tid >> 5, l = tid & 31;
    const int obase = (int)rank * 64 + w * 4;

    // Packed weights: w01[j] = (wuu[o0][l+32j], wuu[o1][l+32j]), w23 likewise.
    ull w01[16], w23[16];
#pragma unroll
    for (int j = 0; j < 16; j++) {
        w01[j] = pack2_(wuu[(obase + 0) * RDIM + l + 32 * j],
                        wuu[(obase + 1) * RDIM + l + 32 * j]);
        w23[j] = pack2_(wuu[(obase + 2) * RDIM + l + 32 * j],
                        wuu[(obase + 3) * RDIM + l + 32 * j]);
    }

    const uint32_t mb0 = smem_u32(&mbar[0]);
    const uint32_t mb1 = smem_u32(&mbar[1]);
    if (tid == 0) {
        MBAR_INIT(mb0, 512);
        MBAR_INIT(mb1, 512);
    }
    {
        float ui = u0[tid];
        u_d[0][tid] = dup2_(ui);
        if (rank == 0) uprev[tid] = ui;
    }
    __syncthreads();
    cluster_sync_();   // barriers + initial buffer visible cluster-wide

    for (int t = 0; t < NTT - 1; t++) {
        const int rb = t % 3;
        const int wb = (t + 1) % 3;

        float av = 0.f;
        if (l < 4) av = a[t * RDIM + obase + l];

        const ull* us = u_d[rb];
        ull s01 = 0ull, s23 = 0ull;
#pragma unroll
        for (int j = 0; j < 16; j++) {
            ull up = us[l + 32 * j];
            s01 = fma2_(w01[j], up, s01);
            s23 = fma2_(w23[j], up, s23);
        }
#pragma unroll
        for (int off = 16; off; off >>= 1) {
            s01 = add2_(s01, __shfl_xor_sync(0xffffffffu, s01, off));
            s23 = add2_(s23, __shfl_xor_sync(0xffffffffu, s23, off));
        }

        const uint32_t bar = (t & 1) ? mb1 : mb0;
        if (l < 4) {
            float acc = (l == 0) ? lo2_(s01) : (l == 1) ? hi2_(s01)
                      : (l == 2) ? lo2_(s23) : hi2_(s23);
            float un = tanhf(acc + av);
            ull und = dup2_(un);
            uint32_t dst = smem_u32(&u_d[wb][obase + l]);
#pragma unroll
            for (unsigned r = 0; r < 8; r++) {
                uint32_t rem, remb;
                asm volatile("mapa.shared::cluster.u32 %0, %1, %2;"
                             : "=r"(rem) : "r"(dst), "r"(r));
                asm volatile("st.shared::cluster.b64 [%0], %1;"
                             :: "r"(rem), "l"(und) : "memory");
                asm volatile("mapa.shared::cluster.u32 %0, %1, %2;"
                             : "=r"(remb) : "r"(bar), "r"(r));
                MBAR_ARRIVE_REL_CLUSTER(remb);
            }
            uprev[(t + 1) * RDIM + obase + l] = un;
        }
        const uint32_t parity = (t >> 1) & 1;
        WAITP_ACQ_CLUSTER(bar, parity);
    }
}

// ---------------------------------------------------------------------------
// Small utility kernels (unchanged)
// ---------------------------------------------------------------------------
__global__ void transpose_w_kernel(const float* __restrict__ w, float* __restrict__ wT) {
    int idx = blockIdx.x * blockDim.x + threadIdx.x;
    if (idx < HDIM * VDIM) {
        int i = idx / VDIM, j = idx % VDIM;
        wT[j * HDIM + i] = w[idx];
    }
}

__global__ void ce_partial_kernel(const float* __restrict__ visible,
                                  const float* __restrict__ bvt, double* __restrict__ out) {
    __shared__ double sd[256];
    double s = 0.0;
    const int n = NTT * VDIM;
    for (int idx = blockIdx.x * 256 + threadIdx.x; idx < n; idx += gridDim.x * 256) {
        float x = bvt[idx];
        float y = 1.f / (1.f + expf(-x));
        float v = visible[idx + VDIM];
        float term = -(v * logf(1e-6f + y) + (1.f - v) * logf(1e-6f + 1.f - y));
        s += (double)term;
    }
    sd[threadIdx.x] = s;
    __syncthreads();
    for (int o = 128; o; o >>= 1) {
        if (threadIdx.x < o) sd[threadIdx.x] += sd[threadIdx.x + o];
        __syncthreads();
    }
    if (threadIdx.x == 0) out[blockIdx.x] = sd[0];
}

__global__ void sqsum_kernel(const float* __restrict__ x, int n, double* __restrict__ out) {
    __shared__ double sd[256];
    double s = 0.0;
    for (int i = blockIdx.x * 256 + threadIdx.x; i < n; i += gridDim.x * 256) {
        float f = x[i];
        s += (double)f * (double)f;
    }
    sd[threadIdx.x] = s;
    __syncthreads();
    for (int o = 128; o; o >>= 1) {
        if (threadIdx.x < o) sd[threadIdx.x] += sd[threadIdx.x + o];
        __syncthreads();
    }
    if (threadIdx.x == 0) out[blockIdx.x] = sd[0];
}

__global__ void mse_kernel(const float* __restrict__ visible,
                           const float* __restrict__ vneg, float* __restrict__ out) {
    int t = blockIdx.x * blockDim.x + threadIdx.x;
    if (t < NTT) {
        float s = 0.f;
#pragma unroll 8
        for (int j = 0; j < VDIM; j++)
            s += fabsf(visible[(t + 1) * VDIM + j] - vneg[t * VDIM + j]);
        out[1 + t] = s / 88.0f;
    }
}

__global__ void finalize_kernel(const double* __restrict__ ce,
                                const double* __restrict__ n2uv,
                                const double* __restrict__ n2uh,
                                float* __restrict__ out) {
    __shared__ double s[256];
    const int t = threadIdx.x;
    s[t] = ce[t];
    __syncthreads();
    for (int o = 128; o; o >>= 1) { if (t < o) s[t] += s[t + o]; __syncthreads(); }
    double ce_sum = s[0];
    __syncthreads();
    s[t] = (t < 64) ? n2uv[t] : 0.0;
    __syncthreads();
    for (int o = 128; o; o >>= 1) { if (t < o) s[t] += s[t + o]; __syncthreads(); }
    double suv = s[0];
    __syncthreads();
    s[t] = (t < 64) ? n2uh[t] : 0.0;
    __syncthreads();
    for (int o = 128; o; o >>= 1) { if (t < o) s[t] += s[t + o]; __syncthreads(); }
    double suh = s[0];
    if (t == 0) {
        double reg = 0.2 * (sqrt(suv) + sqrt(suh));
        out[0]      = (float)(ce_sum / (double)TSTEPS + reg);
        out[TSTEPS] = (float)reg;
    }
}

// ---------------------------------------------------------------------------
// Launch
// ---------------------------------------------------------------------------
extern "C" void kernel_launch(void* const* d_in, const int* in_sizes, int n_in,
                              void* d_out, int out_size) {
    const float* visible = (const float*)d_in[0];
    const float* rand_h  = (const float*)d_in[1];
    const float* rand_v  = (const float*)d_in[2];
    const float* w       = (const float*)d_in[3];
    const float* wuu     = (const float*)d_in[4];
    const float* wuv     = (const float*)d_in[5];
    const float* wuh     = (const float*)d_in[6];
    const float* wvu     = (const float*)d_in[7];
    const float* bv      = (const float*)d_in[8];
    const float* bh      = (const float*)d_in[9];
    const float* bu      = (const float*)d_in[10];
    const float* u0      = (const float*)d_in[11];
    float* out = (float*)d_out;

    void *pa, *pu, *pbh, *pbv, *ph, *pv, *pwT, *pce, *pnuv, *pnuh;
    cudaGetSymbolAddress(&pa,   g_a);
    cudaGetSymbolAddress(&pu,   g_uprev);
    cudaGetSymbolAddress(&pbh,  g_bht);
    cudaGetSymbolAddress(&pbv,  g_bvt);
    cudaGetSymbolAddress(&ph,   g_h);
    cudaGetSymbolAddress(&pv,   g_v);
    cudaGetSymbolAddress(&pwT,  g_wT);
    cudaGetSymbolAddress(&pce,  g_ce);
    cudaGetSymbolAddress(&pnuv, g_n2uv);
    cudaGetSymbolAddress(&pnuh, g_n2uh);

    // 0) transpose w -> wT (V, H)
    transpose_w_kernel<<<(HDIM * VDIM + 255) / 256, 256>>>(w, (float*)pwT);

    // 1) a[t] = v_seq[t] @ wvu^T + bu   (M=4095, N=512, K=88)
    {
        dim3 g((NTT + 127) / 128, (RDIM + 63) / 64);
        gemm2_nt<8><<<g, 256>>>(visible + VDIM, VDIM, wvu, VDIM,
                                bu, 0, nullptr, 0,
                                (float*)pa, RDIM, NTT, RDIM, VDIM);
    }

    // 2) sequential recurrence -> u_prev
    recur_kernel<<<8, 512>>>(wuu, (const float*)pa, u0, (float*)pu);

    // 3) bh_t = u_prev @ wuh^T + bh ; bv_t = u_prev @ wuv^T + bv
    {
        dim3 g((NTT + 127) / 128, (HDIM + 63) / 64);
        gemm2_nt<8><<<g, 256>>>((const float*)pu, RDIM, wuh, RDIM,
                                bh, 0, nullptr, 0,
                                (float*)pbh, HDIM, NTT, HDIM, RDIM);
        dim3 g2((NTT + 63) / 64, (VDIM + 63) / 64);
        gemm2_nt<4><<<g2, 256>>>((const float*)pu, RDIM, wuv, RDIM,
                                 bv, 0, nullptr, 0,
                                 (float*)pbv, VDIM, NTT, VDIM, RDIM);
    }

    // 4) Gibbs: v starts as v_seq
    cudaMemcpyAsync(pv, visible + VDIM, (size_t)NTT * VDIM * sizeof(float),
                    cudaMemcpyDeviceToDevice, 0);
    {
        dim3 gh((NTT + 127) / 128, (HDIM + 63) / 64);
        dim3 gv((NTT + 63) / 64, (VDIM + 63) / 64);
        for (int s = 0; s < GS; s++) {
            gemm2_nt<8><<<gh, 256>>>((const float*)pv, VDIM, w, VDIM,
                                     (const float*)pbh, HDIM,
                                     rand_h + (size_t)s * HDIM, GS * HDIM,
                                     (float*)ph, HDIM, NTT, HDIM, VDIM);
            gemm2_nt<4><<<gv, 256>>>((const float*)ph, HDIM, (const float*)pwT, HDIM,
                                     (const float*)pbv, VDIM,
                                     rand_v + (size_t)s * VDIM, GS * VDIM,
                                     (float*)pv, VDIM, NTT, VDIM, HDIM);
        }
    }

    // 5) reductions
    ce_partial_kernel<<<256, 256>>>(visible, (const float*)pbv, (double*)pce);
    sqsum_kernel<<<64, 256>>>(wuv, VDIM * RDIM, (double*)pnuv);
    sqsum_kernel<<<64, 256>>>(wuh, HDIM * RDIM, (double*)pnuh);
    mse_kernel<<<(NTT + 255) / 256, 256>>>(visible, (const float*)pv, out);
    finalize_kernel<<<1, 256>>>((const double*)pce, (const double*)pnuv,
                                (const double*)pnuh, out);
}

// round 13
// speedup vs baseline: 2.1495x; 2.1495x over previous
#include <cuda_runtime.h>
#include <cstdint>
#include <cstdio>

#define TSTEPS 4096
#define NTT    4095
#define VDIM   88
#define HDIM   512
#define RDIM   512
#define GS     20

typedef unsigned long long ull;

// ---------------------------------------------------------------------------
// Scratch (static device globals — no runtime allocation allowed)
// ---------------------------------------------------------------------------
__device__ float  g_a    [NTT * RDIM];
__device__ float  g_uprev[NTT * RDIM];
__device__ float  g_bht  [NTT * HDIM];
__device__ float  g_bvt  [NTT * VDIM];
__device__ float  g_h    [NTT * HDIM];
__device__ float  g_v    [NTT * VDIM];
__device__ float  g_wT   [VDIM * HDIM];
__device__ double g_ce   [256];
__device__ double g_n2uv [64];
__device__ double g_n2uh [64];

// ---------------------------------------------------------------------------
// Helpers: packed fp32x2 ops (componentwise IEEE fp32 — order-preserving)
// ---------------------------------------------------------------------------
__device__ __forceinline__ ull fma2_(ull a, ull b, ull c) {
    ull d; asm("fma.rn.f32x2 %0, %1, %2, %3;" : "=l"(d) : "l"(a), "l"(b), "l"(c));
    return d;
}
__device__ __forceinline__ ull add2_(ull a, ull b) {
    ull d; asm("add.rn.f32x2 %0, %1, %2;" : "=l"(d) : "l"(a), "l"(b));
    return d;
}
__device__ __forceinline__ ull pack2_(float lo, float hi) {
    ull d; asm("mov.b64 %0, {%1, %2};" : "=l"(d) : "f"(lo), "f"(hi));
    return d;
}
__device__ __forceinline__ ull dup2_(float v) {
    ull d; asm("mov.b64 %0, {%1, %1};" : "=l"(d) : "f"(v));
    return d;
}
__device__ __forceinline__ float lo2_(ull v) { return __uint_as_float((unsigned)v); }
__device__ __forceinline__ float hi2_(ull v) { return __uint_as_float((unsigned)(v >> 32)); }

__device__ __forceinline__ void cluster_sync_() {
    asm volatile("barrier.cluster.arrive.aligned;\n\t"
                 "barrier.cluster.wait.aligned;" ::: "memory");
}
__device__ __forceinline__ uint32_t smem_u32(const void* p) {
    return (uint32_t)__cvta_generic_to_shared(p);
}

// ---------------------------------------------------------------------------
// NT GEMM: C[m][n] = sum_k A[m][k]*B[n][k] + bias[m*bs+n]; optional Bernoulli
// epilogue. Tile (16*TM) x 64, K-chunk 16, 256 threads, TM x 4 per thread.
// FFMA2 pairs adjacent M rows; each output's k-ascending chain is bit-exact
// vs the round-8 scalar kernel. Requires lda, ldb, K all % 4 == 0 (true for
// every call site: 88 / 512). Register-double-buffered staging, vectorized
// global loads. __launch_bounds__(256,2) keeps regs ~102 (no spills).
// ---------------------------------------------------------------------------
template <int TM>
__global__ void __launch_bounds__(256, 2) gemm2_nt(
    const float* __restrict__ A, int lda,
    const float* __restrict__ B, int ldb,
    const float* __restrict__ bias, int bias_stride,
    const float* __restrict__ rnd, int rnd_stride,
    float* __restrict__ C, int ldc,
    int M, int N, int K)
{
    constexpr int BM  = 16 * TM;
    constexpr int KW  = TM;        // floats per thread (A staging, k dir)
    constexpr int TPR = 16 / KW;   // threads per A row
    constexpr int AQ  = KW / 4;    // float4s per thread (A staging)

    __shared__ __align__(16) float As[16][BM];
    __shared__ __align__(16) float Bs[16][64];

    const int tid = threadIdx.x;
    const int tx  = tid & 15;
    const int ty  = tid >> 4;
    const int m0  = blockIdx.x * BM;
    const int n0  = blockIdx.y * 64;

    // A staging map
    const int arow  = tid / TPR;
    const int akb   = (tid % TPR) * KW;
    const int am    = m0 + arow;
    const bool amok = (am < M);
    // B staging map
    const int brow  = tid >> 2;
    const int bkb   = (tid & 3) * 4;
    const int bn    = n0 + brow;
    const bool bnok = (bn < N);

    const float* Abase = A + (size_t)am * lda;
    const float* Bbase = B + (size_t)bn * ldb;
    const float4 z4 = make_float4(0.f, 0.f, 0.f, 0.f);

    float4 aR[AQ], bR;

    // preload chunk 0
#pragma unroll
    for (int q = 0; q < AQ; q++) {
        int k = akb + q * 4;
        aR[q] = (amok && k < K) ? *(const float4*)(Abase + k) : z4;
    }
    bR = (bnok && bkb < K) ? *(const float4*)(Bbase + bkb) : z4;

    ull acc[TM / 2][4];
#pragma unroll
    for (int i = 0; i < TM / 2; i++)
#pragma unroll
        for (int j = 0; j < 4; j++) acc[i][j] = 0ull;

    for (int k0 = 0; k0 < K; k0 += 16) {
        // commit staged regs to smem
#pragma unroll
        for (int q = 0; q < AQ; q++) {
            As[akb + q * 4 + 0][arow] = aR[q].x;
            As[akb + q * 4 + 1][arow] = aR[q].y;
            As[akb + q * 4 + 2][arow] = aR[q].z;
            As[akb + q * 4 + 3][arow] = aR[q].w;
        }
        Bs[bkb + 0][brow] = bR.x;
        Bs[bkb + 1][brow] = bR.y;
        Bs[bkb + 2][brow] = bR.z;
        Bs[bkb + 3][brow] = bR.w;
        __syncthreads();

        // prefetch next chunk while computing
        const int kn = k0 + 16;
        if (kn < K) {
#pragma unroll
            for (int q = 0; q < AQ; q++) {
                int k = kn + akb + q * 4;
                aR[q] = (amok && k < K) ? *(const float4*)(Abase + k) : z4;
            }
            int kb = kn + bkb;
            bR = (bnok && kb < K) ? *(const float4*)(Bbase + kb) : z4;
        }

#pragma unroll
        for (int k = 0; k < 16; k++) {
            float4 b4 = *(const float4*)&Bs[k][tx * 4];
            ull bb[4];
            bb[0] = dup2_(b4.x); bb[1] = dup2_(b4.y);
            bb[2] = dup2_(b4.z); bb[3] = dup2_(b4.w);
#pragma unroll
            for (int q = 0; q < TM / 4; q++) {
                ulonglong2 aa = *(const ulonglong2*)&As[k][ty * TM + q * 4];
#pragma unroll
                for (int c = 0; c < 4; c++) {
                    acc[2 * q + 0][c] = fma2_(aa.x, bb[c], acc[2 * q + 0][c]);
                    acc[2 * q + 1][c] = fma2_(aa.y, bb[c], acc[2 * q + 1][c]);
                }
            }
        }
        __syncthreads();
    }

    // Epilogue: acc[i] lo -> row ty*TM+2i, hi -> row ty*TM+2i+1
#pragma unroll
    for (int i = 0; i < TM / 2; i++) {
#pragma unroll
        for (int half = 0; half < 2; half++) {
            const int m = m0 + ty * TM + 2 * i + half;
            if (m >= M) continue;
#pragma unroll
            for (int c = 0; c < 4; c++) {
                const int n = n0 + tx * 4 + c;
                if (n >= N) continue;
                float v = half ? hi2_(acc[i][c]) : lo2_(acc[i][c]);
                float val = v + bias[(size_t)m * bias_stride + n];
                if (rnd) {
                    float s = 1.f / (1.f + expf(-val));
                    val = (s > rnd[(size_t)m * rnd_stride + n]) ? 1.f : 0.f;
                }
                C[(size_t)m * ldc + n] = val;
            }
        }
    }
}

// ---------------------------------------------------------------------------
// Sequential u recurrence — REVERTED to the proven R10 structure:
// cluster of 8 CTAs, wuu register-resident (FFMA2-packed), per-step
// butterfly reduce, 8 remote DSMEM stores by lanes l<4, cluster.sync.
// Only change vs R10: u is stored pre-duplicated as (u,u) 64-bit pairs so the
// dot loop consumes LDS.64 directly (no dup MOVs). Same values, same order.
// ---------------------------------------------------------------------------
__global__ void __cluster_dims__(8, 1, 1) __launch_bounds__(512, 1)
recur_kernel(const float* __restrict__ wuu, const float* __restrict__ a,
             const float* __restrict__ u0, float* __restrict__ uprev)
{
    __shared__ __align__(16) ull u_d[2][RDIM];   // (u,u) duplicated pairs

    unsigned rank;
    asm("mov.u32 %0, %%cluster_ctarank;" : "=r"(rank));

    const int tid = threadIdx.x;
    const int w = tid >> 5, l = tid & 31;
    const int obase = (int)rank * 64 + w * 4;

    // Packed weights: w01[j] = (wuu[o0][l+32j], wuu[o1][l+32j]), w23 likewise.
    ull w01[16], w23[16];
#pragma unroll
    for (int j = 0; j < 16; j++) {
        w01[j] = pack2_(wuu[(obase + 0) * RDIM + l + 32 * j],
                        wuu[(obase + 1) * RDIM + l + 32 * j]);
        w23[j] = pack2_(wuu[(obase + 2) * RDIM + l + 32 * j],
                        wuu[(obase + 3) * RDIM + l + 32 * j]);
    }

    {
        float ui = u0[tid];
        u_d[0][tid] = dup2_(ui);
        if (rank == 0) uprev[tid] = ui;
    }

    const uint32_t base0 = smem_u32(&u_d[0][0]);
    const uint32_t base1 = smem_u32(&u_d[1][0]);

    cluster_sync_();

    int p = 0;
    for (int t = 0; t < NTT - 1; t++) {
        float av = 0.f;
        if (l < 4) av = a[t * RDIM + obase + l];

        const ull* us = u_d[p];
        ull s01 = 0ull, s23 = 0ull;
#pragma unroll
        for (int j = 0; j < 16; j++) {
            ull up = us[l + 32 * j];
            s01 = fma2_(w01[j], up, s01);
            s23 = fma2_(w23[j], up, s23);
        }
#pragma unroll
        for (int off = 16; off; off >>= 1) {
            s01 = add2_(s01, __shfl_xor_sync(0xffffffffu, s01, off));
            s23 = add2_(s23, __shfl_xor_sync(0xffffffffu, s23, off));
        }
        if (l < 4) {
            float acc = (l == 0) ? lo2_(s01) : (l == 1) ? hi2_(s01)
                      : (l == 2) ? lo2_(s23) : hi2_(s23);
            float un = tanhf(acc + av);
            ull und = dup2_(un);
            uint32_t dst = (p ? base0 : base1) + 8u * (uint32_t)(obase + l);
#pragma unroll
            for (unsigned r = 0; r < 8; r++) {
                uint32_t rem;
                asm volatile("mapa.shared::cluster.u32 %0, %1, %2;"
                             : "=r"(rem) : "r"(dst), "r"(r));
                asm volatile("st.shared::cluster.b64 [%0], %1;"
                             :: "r"(rem), "l"(und) : "memory");
            }
            uprev[(t + 1) * RDIM + obase + l] = un;
        }
        cluster_sync_();   // arrive=release orders the DSMEM stores
        p ^= 1;
    }
}

// ---------------------------------------------------------------------------
// Small utility kernels (unchanged)
// ---------------------------------------------------------------------------
__global__ void transpose_w_kernel(const float* __restrict__ w, float* __restrict__ wT) {
    int idx = blockIdx.x * blockDim.x + threadIdx.x;
    if (idx < HDIM * VDIM) {
        int i = idx / VDIM, j = idx % VDIM;
        wT[j * HDIM + i] = w[idx];
    }
}

__global__ void ce_partial_kernel(const float* __restrict__ visible,
                                  const float* __restrict__ bvt, double* __restrict__ out) {
    __shared__ double sd[256];
    double s = 0.0;
    const int n = NTT * VDIM;
    for (int idx = blockIdx.x * 256 + threadIdx.x; idx < n; idx += gridDim.x * 256) {
        float x = bvt[idx];
        float y = 1.f / (1.f + expf(-x));
        float v = visible[idx + VDIM];
        float term = -(v * logf(1e-6f + y) + (1.f - v) * logf(1e-6f + 1.f - y));
        s += (double)term;
    }
    sd[threadIdx.x] = s;
    __syncthreads();
    for (int o = 128; o; o >>= 1) {
        if (threadIdx.x < o) sd[threadIdx.x] += sd[threadIdx.x + o];
        __syncthreads();
    }
    if (threadIdx.x == 0) out[blockIdx.x] = sd[0];
}

__global__ void sqsum_kernel(const float* __restrict__ x, int n, double* __restrict__ out) {
    __shared__ double sd[256];
    double s = 0.0;
    for (int i = blockIdx.x * 256 + threadIdx.x; i < n; i += gridDim.x * 256) {
        float f = x[i];
        s += (double)f * (double)f;
    }
    sd[threadIdx.x] = s;
    __syncthreads();
    for (int o = 128; o; o >>= 1) {
        if (threadIdx.x < o) sd[threadIdx.x] += sd[threadIdx.x + o];
        __syncthreads();
    }
    if (threadIdx.x == 0) out[blockIdx.x] = sd[0];
}

__global__ void mse_kernel(const float* __restrict__ visible,
                           const float* __restrict__ vneg, float* __restrict__ out) {
    int t = blockIdx.x * blockDim.x + threadIdx.x;
    if (t < NTT) {
        float s = 0.f;
#pragma unroll 8
        for (int j = 0; j < VDIM; j++)
            s += fabsf(visible[(t + 1) * VDIM + j] - vneg[t * VDIM + j]);
        out[1 + t] = s / 88.0f;
    }
}

__global__ void finalize_kernel(const double* __restrict__ ce,
                                const double* __restrict__ n2uv,
                                const double* __restrict__ n2uh,
                                float* __restrict__ out) {
    __shared__ double s[256];
    const int t = threadIdx.x;
    s[t] = ce[t];
    __syncthreads();
    for (int o = 128; o; o >>= 1) { if (t < o) s[t] += s[t + o]; __syncthreads(); }
    double ce_sum = s[0];
    __syncthreads();
    s[t] = (t < 64) ? n2uv[t] : 0.0;
    __syncthreads();
    for (int o = 128; o; o >>= 1) { if (t < o) s[t] += s[t + o]; __syncthreads(); }
    double suv = s[0];
    __syncthreads();
    s[t] = (t < 64) ? n2uh[t] : 0.0;
    __syncthreads();
    for (int o = 128; o; o >>= 1) { if (t < o) s[t] += s[t + o]; __syncthreads(); }
    double suh = s[0];
    if (t == 0) {
        double reg = 0.2 * (sqrt(suv) + sqrt(suh));
        out[0]      = (float)(ce_sum / (double)TSTEPS + reg);
        out[TSTEPS] = (float)reg;
    }
}

// ---------------------------------------------------------------------------
// Launch
// ---------------------------------------------------------------------------
extern "C" void kernel_launch(void* const* d_in, const int* in_sizes, int n_in,
                              void* d_out, int out_size) {
    const float* visible = (const float*)d_in[0];
    const float* rand_h  = (const float*)d_in[1];
    const float* rand_v  = (const float*)d_in[2];
    const float* w       = (const float*)d_in[3];
    const float* wuu     = (const float*)d_in[4];
    const float* wuv     = (const float*)d_in[5];
    const float* wuh     = (const float*)d_in[6];
    const float* wvu     = (const float*)d_in[7];
    const float* bv      = (const float*)d_in[8];
    const float* bh      = (const float*)d_in[9];
    const float* bu      = (const float*)d_in[10];
    const float* u0      = (const float*)d_in[11];
    float* out = (float*)d_out;

    void *pa, *pu, *pbh, *pbv, *ph, *pv, *pwT, *pce, *pnuv, *pnuh;
    cudaGetSymbolAddress(&pa,   g_a);
    cudaGetSymbolAddress(&pu,   g_uprev);
    cudaGetSymbolAddress(&pbh,  g_bht);
    cudaGetSymbolAddress(&pbv,  g_bvt);
    cudaGetSymbolAddress(&ph,   g_h);
    cudaGetSymbolAddress(&pv,   g_v);
    cudaGetSymbolAddress(&pwT,  g_wT);
    cudaGetSymbolAddress(&pce,  g_ce);
    cudaGetSymbolAddress(&pnuv, g_n2uv);
    cudaGetSymbolAddress(&pnuh, g_n2uh);

    // 0) transpose w -> wT (V, H)
    transpose_w_kernel<<<(HDIM * VDIM + 255) / 256, 256>>>(w, (float*)pwT);

    // 1) a[t] = v_seq[t] @ wvu^T + bu   (M=4095, N=512, K=88)
    {
        dim3 g((NTT + 127) / 128, (RDIM + 63) / 64);
        gemm2_nt<8><<<g, 256>>>(visible + VDIM, VDIM, wvu, VDIM,
                                bu, 0, nullptr, 0,
                                (float*)pa, RDIM, NTT, RDIM, VDIM);
    }

    // 2) sequential recurrence -> u_prev
    recur_kernel<<<8, 512>>>(wuu, (const float*)pa, u0, (float*)pu);

    // 3) bh_t = u_prev @ wuh^T + bh ; bv_t = u_prev @ wuv^T + bv
    {
        dim3 g((NTT + 127) / 128, (HDIM + 63) / 64);
        gemm2_nt<8><<<g, 256>>>((const float*)pu, RDIM, wuh, RDIM,
                                bh, 0, nullptr, 0,
                                (float*)pbh, HDIM, NTT, HDIM, RDIM);
        dim3 g2((NTT + 63) / 64, (VDIM + 63) / 64);
        gemm2_nt<4><<<g2, 256>>>((const float*)pu, RDIM, wuv, RDIM,
                                 bv, 0, nullptr, 0,
                                 (float*)pbv, VDIM, NTT, VDIM, RDIM);
    }

    // 4) Gibbs: v starts as v_seq
    cudaMemcpyAsync(pv, visible + VDIM, (size_t)NTT * VDIM * sizeof(float),
                    cudaMemcpyDeviceToDevice, 0);
    {
        dim3 gh((NTT + 127) / 128, (HDIM + 63) / 64);
        dim3 gv((NTT + 63) / 64, (VDIM + 63) / 64);
        for (int s = 0; s < GS; s++) {
            gemm2_nt<8><<<gh, 256>>>((const float*)pv, VDIM, w, VDIM,
                                     (const float*)pbh, HDIM,
                                     rand_h + (size_t)s * HDIM, GS * HDIM,
                                     (float*)ph, HDIM, NTT, HDIM, VDIM);
            gemm2_nt<4><<<gv, 256>>>((const float*)ph, HDIM, (const float*)pwT, HDIM,
                                     (const float*)pbv, VDIM,
                                     rand_v + (size_t)s * VDIM, GS * VDIM,
                                     (float*)pv, VDIM, NTT, VDIM, HDIM);
        }
    }

    // 5) reductions
    ce_partial_kernel<<<256, 256>>>(visible, (const float*)pbv, (double*)pce);
    sqsum_kernel<<<64, 256>>>(wuv, VDIM * RDIM, (double*)pnuv);
    sqsum_kernel<<<64, 256>>>(wuh, HDIM * RDIM, (double*)pnuh);
    mse_kernel<<<(NTT + 255) / 256, 256>>>(visible, (const float*)pv, out);
    finalize_kernel<<<1, 256>>>((const double*)pce, (const double*)pnuv,
                                (const double*)pnuh, out);
}

// round 14
// speedup vs baseline: 2.1943x; 1.0209x over previous
#include <cuda_runtime.h>
#include <cstdint>
#include <cstdio>

#define TSTEPS 4096
#define NTT    4095
#define VDIM   88
#define HDIM   512
#define RDIM   512
#define GS     20

typedef unsigned long long ull;

// ---------------------------------------------------------------------------
// Scratch (static device globals — no runtime allocation allowed)
// ---------------------------------------------------------------------------
__device__ float  g_a    [NTT * RDIM];
__device__ float  g_uprev[NTT * RDIM];
__device__ float  g_bht  [NTT * HDIM];
__device__ float  g_bvt  [NTT * VDIM];
__device__ double g_ce   [256];
__device__ double g_n2uv [64];
__device__ double g_n2uh [64];

// ---------------------------------------------------------------------------
// Helpers: packed fp32x2 ops (componentwise IEEE fp32 — order-preserving)
// ---------------------------------------------------------------------------
__device__ __forceinline__ ull fma2_(ull a, ull b, ull c) {
    ull d; asm("fma.rn.f32x2 %0, %1, %2, %3;" : "=l"(d) : "l"(a), "l"(b), "l"(c));
    return d;
}
__device__ __forceinline__ ull add2_(ull a, ull b) {
    ull d; asm("add.rn.f32x2 %0, %1, %2;" : "=l"(d) : "l"(a), "l"(b));
    return d;
}
__device__ __forceinline__ ull pack2_(float lo, float hi) {
    ull d; asm("mov.b64 %0, {%1, %2};" : "=l"(d) : "f"(lo), "f"(hi));
    return d;
}
__device__ __forceinline__ ull dup2_(float v) {
    ull d; asm("mov.b64 %0, {%1, %1};" : "=l"(d) : "f"(v));
    return d;
}
__device__ __forceinline__ float lo2_(ull v) { return __uint_as_float((unsigned)v); }
__device__ __forceinline__ float hi2_(ull v) { return __uint_as_float((unsigned)(v >> 32)); }

__device__ __forceinline__ void cluster_sync_() {
    asm volatile("barrier.cluster.arrive.aligned;\n\t"
                 "barrier.cluster.wait.aligned;" ::: "memory");
}
__device__ __forceinline__ uint32_t smem_u32(const void* p) {
    return (uint32_t)__cvta_generic_to_shared(p);
}

// ---------------------------------------------------------------------------
// NT GEMM (unchanged from R13): C = A*B^T + bias, optional Bernoulli epilogue.
// ---------------------------------------------------------------------------
template <int TM>
__global__ void __launch_bounds__(256, 2) gemm2_nt(
    const float* __restrict__ A, int lda,
    const float* __restrict__ B, int ldb,
    const float* __restrict__ bias, int bias_stride,
    const float* __restrict__ rnd, int rnd_stride,
    float* __restrict__ C, int ldc,
    int M, int N, int K)
{
    constexpr int BM  = 16 * TM;
    constexpr int KW  = TM;
    constexpr int TPR = 16 / KW;
    constexpr int AQ  = KW / 4;

    __shared__ __align__(16) float As[16][BM];
    __shared__ __align__(16) float Bs[16][64];

    const int tid = threadIdx.x;
    const int tx  = tid & 15;
    const int ty  = tid >> 4;
    const int m0  = blockIdx.x * BM;
    const int n0  = blockIdx.y * 64;

    const int arow  = tid / TPR;
    const int akb   = (tid % TPR) * KW;
    const int am    = m0 + arow;
    const bool amok = (am < M);
    const int brow  = tid >> 2;
    const int bkb   = (tid & 3) * 4;
    const int bn    = n0 + brow;
    const bool bnok = (bn < N);

    const float* Abase = A + (size_t)am * lda;
    const float* Bbase = B + (size_t)bn * ldb;
    const float4 z4 = make_float4(0.f, 0.f, 0.f, 0.f);

    float4 aR[AQ], bR;

#pragma unroll
    for (int q = 0; q < AQ; q++) {
        int k = akb + q * 4;
        aR[q] = (amok && k < K) ? *(const float4*)(Abase + k) : z4;
    }
    bR = (bnok && bkb < K) ? *(const float4*)(Bbase + bkb) : z4;

    ull acc[TM / 2][4];
#pragma unroll
    for (int i = 0; i < TM / 2; i++)
#pragma unroll
        for (int j = 0; j < 4; j++) acc[i][j] = 0ull;

    for (int k0 = 0; k0 < K; k0 += 16) {
#pragma unroll
        for (int q = 0; q < AQ; q++) {
            As[akb + q * 4 + 0][arow] = aR[q].x;
            As[akb + q * 4 + 1][arow] = aR[q].y;
            As[akb + q * 4 + 2][arow] = aR[q].z;
            As[akb + q * 4 + 3][arow] = aR[q].w;
        }
        Bs[bkb + 0][brow] = bR.x;
        Bs[bkb + 1][brow] = bR.y;
        Bs[bkb + 2][brow] = bR.z;
        Bs[bkb + 3][brow] = bR.w;
        __syncthreads();

        const int kn = k0 + 16;
        if (kn < K) {
#pragma unroll
            for (int q = 0; q < AQ; q++) {
                int k = kn + akb + q * 4;
                aR[q] = (amok && k < K) ? *(const float4*)(Abase + k) : z4;
            }
            int kb = kn + bkb;
            bR = (bnok && kb < K) ? *(const float4*)(Bbase + kb) : z4;
        }

#pragma unroll
        for (int k = 0; k < 16; k++) {
            float4 b4 = *(const float4*)&Bs[k][tx * 4];
            ull bb[4];
            bb[0] = dup2_(b4.x); bb[1] = dup2_(b4.y);
            bb[2] = dup2_(b4.z); bb[3] = dup2_(b4.w);
#pragma unroll
            for (int q = 0; q < TM / 4; q++) {
                ulonglong2 aa = *(const ulonglong2*)&As[k][ty * TM + q * 4];
#pragma unroll
                for (int c = 0; c < 4; c++) {
                    acc[2 * q + 0][c] = fma2_(aa.x, bb[c], acc[2 * q + 0][c]);
                    acc[2 * q + 1][c] = fma2_(aa.y, bb[c], acc[2 * q + 1][c]);
                }
            }
        }
        __syncthreads();
    }

#pragma unroll
    for (int i = 0; i < TM / 2; i++) {
#pragma unroll
        for (int half = 0; half < 2; half++) {
            const int m = m0 + ty * TM + 2 * i + half;
            if (m >= M) continue;
#pragma unroll
            for (int c = 0; c < 4; c++) {
                const int n = n0 + tx * 4 + c;
                if (n >= N) continue;
                float v = half ? hi2_(acc[i][c]) : lo2_(acc[i][c]);
                float val = v + bias[(size_t)m * bias_stride + n];
                if (rnd) {
                    float s = 1.f / (1.f + expf(-val));
                    val = (s > rnd[(size_t)m * rnd_stride + n]) ? 1.f : 0.f;
                }
                C[(size_t)m * ldc + n] = val;
            }
        }
    }
}

// ---------------------------------------------------------------------------
// Sequential u recurrence (unchanged, proven).
// ---------------------------------------------------------------------------
__global__ void __cluster_dims__(8, 1, 1) __launch_bounds__(512, 1)
recur_kernel(const float* __restrict__ wuu, const float* __restrict__ a,
             const float* __restrict__ u0, float* __restrict__ uprev)
{
    __shared__ __align__(16) ull u_d[2][RDIM];

    unsigned rank;
    asm("mov.u32 %0, %%cluster_ctarank;" : "=r"(rank));

    const int tid = threadIdx.x;
    const int w = tid >> 5, l = tid & 31;
    const int obase = (int)rank * 64 + w * 4;

    ull w01[16], w23[16];
#pragma unroll
    for (int j = 0; j < 16; j++) {
        w01[j] = pack2_(wuu[(obase + 0) * RDIM + l + 32 * j],
                        wuu[(obase + 1) * RDIM + l + 32 * j]);
        w23[j] = pack2_(wuu[(obase + 2) * RDIM + l + 32 * j],
                        wuu[(obase + 3) * RDIM + l + 32 * j]);
    }

    {
        float ui = u0[tid];
        u_d[0][tid] = dup2_(ui);
        if (rank == 0) uprev[tid] = ui;
    }

    const uint32_t base0 = smem_u32(&u_d[0][0]);
    const uint32_t base1 = smem_u32(&u_d[1][0]);

    cluster_sync_();

    int p = 0;
    for (int t = 0; t < NTT - 1; t++) {
        float av = 0.f;
        if (l < 4) av = a[t * RDIM + obase + l];

        const ull* us = u_d[p];
        ull s01 = 0ull, s23 = 0ull;
#pragma unroll
        for (int j = 0; j < 16; j++) {
            ull up = us[l + 32 * j];
            s01 = fma2_(w01[j], up, s01);
            s23 = fma2_(w23[j], up, s23);
        }
#pragma unroll
        for (int off = 16; off; off >>= 1) {
            s01 = add2_(s01, __shfl_xor_sync(0xffffffffu, s01, off));
            s23 = add2_(s23, __shfl_xor_sync(0xffffffffu, s23, off));
        }
        if (l < 4) {
            float acc = (l == 0) ? lo2_(s01) : (l == 1) ? hi2_(s01)
                      : (l == 2) ? lo2_(s23) : hi2_(s23);
            float un = tanhf(acc + av);
            ull und = dup2_(un);
            uint32_t dst = (p ? base0 : base1) + 8u * (uint32_t)(obase + l);
#pragma unroll
            for (unsigned r = 0; r < 8; r++) {
                uint32_t rem;
                asm volatile("mapa.shared::cluster.u32 %0, %1, %2;"
                             : "=r"(rem) : "r"(dst), "r"(r));
                asm volatile("st.shared::cluster.b64 [%0], %1;"
                             :: "r"(rem), "l"(und) : "memory");
            }
            uprev[(t + 1) * RDIM + obase + l] = un;
        }
        cluster_sync_();
        p ^= 1;
    }
}

// ---------------------------------------------------------------------------
// Fused sparse Gibbs kernel.
//
// v and h are binary, so each GEMM pre-activation equals the sum of the
// w-entries at the nonzero positions, accumulated in ascending k order —
// bit-identical to the dense fma chain (fma(0,w,acc)=acc, fma(1,w,acc)=
// add.rn(acc,w)). Per CTA: w resident in smem, pitch 89 floats:
//   h-phase (thread j, lanes vary j): addr stride 89 words (odd) -> no
//   bank conflicts; v-phase (lanes vary i, consecutive) -> conflict-free.
// Bits -> ascending index lists via ballot + popc prefix scan; lists padded
// to x4 with offsets into zeroed pad column/row (exact no-ops).
// mse computed in-kernel as popcount(v XOR v_seq)/88.
// ---------------------------------------------------------------------------
#define ROWS_PER_CTA 28
#define RB 4
#define WPITCH 89
#define W_FLOATS (512 * WPITCH + 96)   // +96 zero pad row (for h_list pad offset)
#define PAD_VOFF (88 * 4)              // pad column offset (bytes) within a w row
#define PAD_HOFF (512 * WPITCH * 4)    // pad row offset (bytes)

__global__ void __launch_bounds__(512, 1) gibbs_fused(
    const float* __restrict__ visible,
    const float* __restrict__ rand_h,
    const float* __restrict__ rand_v,
    const float* __restrict__ w,       // [512][88]
    const float* __restrict__ bht,     // [NTT][512]
    const float* __restrict__ bvt,     // [NTT][88]
    float* __restrict__ out)           // mse -> out[1 + row]
{
    extern __shared__ __align__(16) char smraw[];
    float*    w_s       = (float*)smraw;
    int*      h_list    = (int*)(w_s + W_FLOATS);          // [RB][520]
    int*      v_list    = h_list + RB * 520;               // [RB][96]
    unsigned* h_cnt     = (unsigned*)(v_list + RB * 96);   // [RB]
    unsigned* v_cnt     = h_cnt + RB;                      // [RB]
    unsigned* vis_words = v_cnt + RB;                      // [RB][3]
    unsigned* v_words   = vis_words + RB * 3;              // [RB][3]
    unsigned* h_words   = v_words + RB * 3;                // [RB][16]

    const int tid  = threadIdx.x;
    const int wid  = tid >> 5;
    const int lane = tid & 31;

    const int base = blockIdx.x * ROWS_PER_CTA;
    const int rcnt = min(ROWS_PER_CTA, NTT - base);
    if (rcnt <= 0) return;

    // Load w into smem (pitch 89); pad column + pad row zeroed.
    for (int idx = tid; idx < W_FLOATS; idx += 512) w_s[idx] = 0.f;
    __syncthreads();
    for (int idx = tid; idx < 512 * 88; idx += 512) {
        int j = idx / 88, i = idx - j * 88;
        w_s[j * WPITCH + i] = w[idx];
    }
    __syncthreads();

    for (int b0 = 0; b0 < rcnt; b0 += RB) {
        // -- init v bits + lists from visible (v_seq = visible[row+1]) --
        if (wid < RB) {
            const int r = wid;
            const int row = base + b0 + r;
            const bool valid = (b0 + r < rcnt);
            unsigned wds[3];
#pragma unroll
            for (int it = 0; it < 3; it++) {
                int i = it * 32 + lane;
                bool bit = valid && (i < VDIM) &&
                           (visible[(size_t)(row + 1) * VDIM + i] > 0.5f);
                wds[it] = __ballot_sync(0xffffffffu, bit);
            }
            if (lane < 3) { vis_words[r * 3 + lane] = wds[lane]; v_words[r * 3 + lane] = wds[lane]; }
            unsigned c = (lane < 3) ? __popc(wds[lane]) : 0;
            unsigned p0 = __shfl_sync(0xffffffffu, c, 0);
            unsigned p1 = __shfl_sync(0xffffffffu, c, 1);
            unsigned p2 = __shfl_sync(0xffffffffu, c, 2);
            unsigned total = p0 + p1 + p2;
            if (lane < 3) {
                unsigned pos = (lane == 0) ? 0 : (lane == 1) ? p0 : p0 + p1;
                unsigned x = wds[lane];
                while (x) {
                    int b = __ffs(x) - 1;
                    v_list[r * 96 + pos++] = (lane * 32 + b) * 4;
                    x &= x - 1;
                }
            }
            if (lane == 0) {
                unsigned t4 = (total + 3) & ~3u;
                for (unsigned q = total; q < t4; q++) v_list[r * 96 + q] = PAD_VOFF;
                v_cnt[r] = t4;
            }
        }
        __syncthreads();

        for (int s = 0; s < GS; s++) {
            // ---------------- h-phase: thread j = tid, rows r = 0..RB-1 ----
            {
                const int j = tid;
                float bh4[RB], rh4[RB], accs[RB];
#pragma unroll
                for (int r = 0; r < RB; r++) {
                    const int row = base + b0 + r;
                    const bool valid = (b0 + r < rcnt);
                    bh4[r] = valid ? bht[(size_t)row * HDIM + j] : 0.f;
                    rh4[r] = valid ? rand_h[((size_t)row * GS + s) * HDIM + j] : 2.f;
                }
                const char* wj = (const char*)(w_s + j * WPITCH);
#pragma unroll
                for (int r = 0; r < RB; r++) {
                    float acc = 0.f;
                    const int n = (int)v_cnt[r];
                    const int* lst = v_list + r * 96;
                    for (int m = 0; m < n; m += 4) {
                        int4 o = *(const int4*)(lst + m);
                        acc += *(const float*)(wj + o.x);
                        acc += *(const float*)(wj + o.y);
                        acc += *(const float*)(wj + o.z);
                        acc += *(const float*)(wj + o.w);
                    }
                    accs[r] = acc;
                }
#pragma unroll
                for (int r = 0; r < RB; r++) {
                    float pre = accs[r] + bh4[r];
                    float sg = 1.f / (1.f + expf(-pre));
                    bool bit = sg > rh4[r];
                    unsigned m = __ballot_sync(0xffffffffu, bit);
                    if (lane == 0) h_words[r * 16 + wid] = m;
                }
            }
            __syncthreads();

            // ---------------- build h lists (warp r) ----------------------
            if (wid < RB) {
                const int r = wid;
                unsigned wd = (lane < 16) ? h_words[r * 16 + lane] : 0u;
                unsigned c = __popc(wd);
                unsigned sc = c;
#pragma unroll
                for (int o = 1; o < 16; o <<= 1) {
                    unsigned v = __shfl_up_sync(0xffffffffu, sc, o);
                    if (lane >= o) sc += v;
                }
                unsigned total = __shfl_sync(0xffffffffu, sc, 15);
                if (lane < 16) {
                    unsigned pos = sc - c;
                    unsigned x = wd;
                    while (x) {
                        int b = __ffs(x) - 1;
                        h_list[r * 520 + pos++] = (lane * 32 + b) * (WPITCH * 4);
                        x &= x - 1;
                    }
                }
                if (lane == 0) {
                    unsigned t4 = (total + 3) & ~3u;
                    for (unsigned q = total; q < t4; q++) h_list[r * 520 + q] = PAD_HOFF;
                    h_cnt[r] = t4;
                }
            }
            __syncthreads();

            // ---------------- v-phase: r = tid/96, i = tid%96 --------------
            {
                const int r = tid / 96;
                const int i = tid - r * 96;
                const bool inr = (r < RB);
                const int row = base + b0 + (inr ? r : 0);
                const bool act = inr && (i < VDIM) && (b0 + r < rcnt);
                float bv = act ? bvt[(size_t)row * VDIM + i] : 0.f;
                float rv = act ? rand_v[((size_t)row * GS + s) * VDIM + i] : 2.f;
                float acc = 0.f;
                if (inr) {
                    const int n = (int)h_cnt[r];
                    const int* lst = h_list + r * 520;
                    const char* wb = (const char*)w_s + i * 4;
                    for (int m = 0; m < n; m += 4) {
                        int4 o = *(const int4*)(lst + m);
                        acc += *(const float*)(wb + o.x);
                        acc += *(const float*)(wb + o.y);
                        acc += *(const float*)(wb + o.z);
                        acc += *(const float*)(wb + o.w);
                    }
                }
                float pre = acc + bv;
                float sg = 1.f / (1.f + expf(-pre));
                bool bit = sg > rv;
                unsigned m = __ballot_sync(0xffffffffu, bit);
                if (lane == 0 && wid < 12) {
                    v_words[(wid / 3) * 3 + (wid % 3)] = m;
                }
            }
            __syncthreads();

            // ---------------- rebuild v lists (warp r) ---------------------
            if (wid < RB) {
                const int r = wid;
                unsigned wd = (lane < 3) ? v_words[r * 3 + lane] : 0u;
                unsigned c = (lane < 3) ? __popc(wd) : 0;
                unsigned p0 = __shfl_sync(0xffffffffu, c, 0);
                unsigned p1 = __shfl_sync(0xffffffffu, c, 1);
                unsigned p2 = __shfl_sync(0xffffffffu, c, 2);
                unsigned total = p0 + p1 + p2;
                if (lane < 3) {
                    unsigned pos = (lane == 0) ? 0 : (lane == 1) ? p0 : p0 + p1;
                    unsigned x = wd;
                    while (x) {
                        int b = __ffs(x) - 1;
                        v_list[r * 96 + pos++] = (lane * 32 + b) * 4;
                        x &= x - 1;
                    }
                }
                if (lane == 0) {
                    unsigned t4 = (total + 3) & ~3u;
                    for (unsigned q = total; q < t4; q++) v_list[r * 96 + q] = PAD_VOFF;
                    v_cnt[r] = t4;
                }
            }
            __syncthreads();
        }

        // -------- mse for this batch: popcount(v ^ v_seq)/88 ---------------
        if (wid < RB && (b0 + wid) < rcnt) {
            const int r = wid;
            const int row = base + b0 + r;
            unsigned d = (lane < 3) ? __popc(v_words[r * 3 + lane] ^ vis_words[r * 3 + lane]) : 0;
            d += __shfl_down_sync(0xffffffffu, d, 1);
            d += __shfl_down_sync(0xffffffffu, d, 2);
            if (lane == 0) out[1 + row] = (float)d / 88.0f;
        }
        __syncthreads();
    }
}

// ---------------------------------------------------------------------------
// Small utility kernels
// ---------------------------------------------------------------------------
__global__ void ce_partial_kernel(const float* __restrict__ visible,
                                  const float* __restrict__ bvt, double* __restrict__ out) {
    __shared__ double sd[256];
    double s = 0.0;
    const int n = NTT * VDIM;
    for (int idx = blockIdx.x * 256 + threadIdx.x; idx < n; idx += gridDim.x * 256) {
        float x = bvt[idx];
        float y = 1.f / (1.f + expf(-x));
        float v = visible[idx + VDIM];
        float term = -(v * logf(1e-6f + y) + (1.f - v) * logf(1e-6f + 1.f - y));
        s += (double)term;
    }
    sd[threadIdx.x] = s;
    __syncthreads();
    for (int o = 128; o; o >>= 1) {
        if (threadIdx.x < o) sd[threadIdx.x] += sd[threadIdx.x + o];
        __syncthreads();
    }
    if (threadIdx.x == 0) out[blockIdx.x] = sd[0];
}

__global__ void sqsum_kernel(const float* __restrict__ x, int n, double* __restrict__ out) {
    __shared__ double sd[256];
    double s = 0.0;
    for (int i = blockIdx.x * 256 + threadIdx.x; i < n; i += gridDim.x * 256) {
        float f = x[i];
        s += (double)f * (double)f;
    }
    sd[threadIdx.x] = s;
    __syncthreads();
    for (int o = 128; o; o >>= 1) {
        if (threadIdx.x < o) sd[threadIdx.x] += sd[threadIdx.x + o];
        __syncthreads();
    }
    if (threadIdx.x == 0) out[blockIdx.x] = sd[0];
}

__global__ void finalize_kernel(const double* __restrict__ ce,
                                const double* __restrict__ n2uv,
                                const double* __restrict__ n2uh,
                                float* __restrict__ out) {
    __shared__ double s[256];
    const int t = threadIdx.x;
    s[t] = ce[t];
    __syncthreads();
    for (int o = 128; o; o >>= 1) { if (t < o) s[t] += s[t + o]; __syncthreads(); }
    double ce_sum = s[0];
    __syncthreads();
    s[t] = (t < 64) ? n2uv[t] : 0.0;
    __syncthreads();
    for (int o = 128; o; o >>= 1) { if (t < o) s[t] += s[t + o]; __syncthreads(); }
    double suv = s[0];
    __syncthreads();
    s[t] = (t < 64) ? n2uh[t] : 0.0;
    __syncthreads();
    for (int o = 128; o; o >>= 1) { if (t < o) s[t] += s[t + o]; __syncthreads(); }
    double suh = s[0];
    if (t == 0) {
        double reg = 0.2 * (sqrt(suv) + sqrt(suh));
        out[0]      = (float)(ce_sum / (double)TSTEPS + reg);
        out[TSTEPS] = (float)reg;
    }
}

// ---------------------------------------------------------------------------
// Launch
// ---------------------------------------------------------------------------
extern "C" void kernel_launch(void* const* d_in, const int* in_sizes, int n_in,
                              void* d_out, int out_size) {
    const float* visible = (const float*)d_in[0];
    const float* rand_h  = (const float*)d_in[1];
    const float* rand_v  = (const float*)d_in[2];
    const float* w       = (const float*)d_in[3];
    const float* wuu     = (const float*)d_in[4];
    const float* wuv     = (const float*)d_in[5];
    const float* wuh     = (const float*)d_in[6];
    const float* wvu     = (const float*)d_in[7];
    const float* bv      = (const float*)d_in[8];
    const float* bh      = (const float*)d_in[9];
    const float* bu      = (const float*)d_in[10];
    const float* u0      = (const float*)d_in[11];
    float* out = (float*)d_out;

    void *pa, *pu, *pbh, *pbv, *pce, *pnuv, *pnuh;
    cudaGetSymbolAddress(&pa,   g_a);
    cudaGetSymbolAddress(&pu,   g_uprev);
    cudaGetSymbolAddress(&pbh,  g_bht);
    cudaGetSymbolAddress(&pbv,  g_bvt);
    cudaGetSymbolAddress(&pce,  g_ce);
    cudaGetSymbolAddress(&pnuv, g_n2uv);
    cudaGetSymbolAddress(&pnuh, g_n2uh);

    // 1) a[t] = v_seq[t] @ wvu^T + bu   (M=4095, N=512, K=88)
    {
        dim3 g((NTT + 127) / 128, (RDIM + 63) / 64);
        gemm2_nt<8><<<g, 256>>>(visible + VDIM, VDIM, wvu, VDIM,
                                bu, 0, nullptr, 0,
                                (float*)pa, RDIM, NTT, RDIM, VDIM);
    }

    // 2) sequential recurrence -> u_prev
    recur_kernel<<<8, 512>>>(wuu, (const float*)pa, u0, (float*)pu);

    // 3) bh_t = u_prev @ wuh^T + bh ; bv_t = u_prev @ wuv^T + bv
    {
        dim3 g((NTT + 127) / 128, (HDIM + 63) / 64);
        gemm2_nt<8><<<g, 256>>>((const float*)pu, RDIM, wuh, RDIM,
                                bh, 0, nullptr, 0,
                                (float*)pbh, HDIM, NTT, HDIM, RDIM);
        dim3 g2((NTT + 63) / 64, (VDIM + 63) / 64);
        gemm2_nt<4><<<g2, 256>>>((const float*)pu, RDIM, wuv, RDIM,
                                 bv, 0, nullptr, 0,
                                 (float*)pbv, VDIM, NTT, VDIM, RDIM);
    }

    // 4) Fused sparse Gibbs (all 20 steps) + mse in one launch
    {
        const int smem = (W_FLOATS + RB * 520 + RB * 96) * 4 + (RB * 2 + RB * 6 + RB * 16 + 8) * 4;
        cudaFuncSetAttribute(gibbs_fused, cudaFuncAttributeMaxDynamicSharedMemorySize, smem);
        const int grid = (NTT + ROWS_PER_CTA - 1) / ROWS_PER_CTA;  // 147
        gibbs_fused<<<grid, 512, smem>>>(visible, rand_h, rand_v, w,
                                         (const float*)pbh, (const float*)pbv, out);
    }

    // 5) reductions
    ce_partial_kernel<<<256, 256>>>(visible, (const float*)pbv, (double*)pce);
    sqsum_kernel<<<64, 256>>>(wuv, VDIM * RDIM, (double*)pnuv);
    sqsum_kernel<<<64, 256>>>(wuh, HDIM * RDIM, (double*)pnuh);
    finalize_kernel<<<1, 256>>>((const double*)pce, (const double*)pnuv,
                                (const double*)pnuh, out);
}